// round 1
// baseline (speedup 1.0000x reference)
#include <cuda_runtime.h>
#include <math.h>

#define BB   2
#define TT   2048
#define DD   2048
#define NH   16
#define NKV  4
#define HDIM 128

// Scratch (allocation-free rule: __device__ globals)
__device__ float g_q[BB*TT*NH*HDIM];    // [B*T, 2048]
__device__ float g_k[BB*TT*NKV*HDIM];   // [B*T, 512]
__device__ float g_v[BB*TT*NKV*HDIM];   // [B*T, 512]
__device__ float g_o[BB*TT*NH*HDIM];    // [B*T, 2048]

// ---------------------------------------------------------------------------
// SGEMM: C[M,N] = A[M,K] @ B[K,N], all row-major, M%128==0, N%128==0, K%8==0
// ---------------------------------------------------------------------------
__global__ __launch_bounds__(256, 2)
void sgemm_kernel(const float* __restrict__ A, const float* __restrict__ B,
                  float* __restrict__ C, int M, int N, int K) {
    __shared__ float As[8][132];  // transposed A tile, padded
    __shared__ float Bs[8][132];

    const int tid = threadIdx.x;
    const int tx = tid & 15;
    const int ty = tid >> 4;
    const int bx = blockIdx.x;
    const int by = blockIdx.y;

    const float* Ab = A + (size_t)by * 128 * K;
    const float* Bb = B + (size_t)bx * 128;

    float acc[8][8] = {};

    const int arow = tid >> 1;          // 0..127
    const int acol = (tid & 1) << 2;    // 0 or 4
    const int brow = tid >> 5;          // 0..7
    const int bcol = (tid & 31) << 2;   // 0..124

    for (int k0 = 0; k0 < K; k0 += 8) {
        float4 av = *(const float4*)(Ab + (size_t)arow * K + k0 + acol);
        As[acol + 0][arow] = av.x;
        As[acol + 1][arow] = av.y;
        As[acol + 2][arow] = av.z;
        As[acol + 3][arow] = av.w;
        *(float4*)&Bs[brow][bcol] =
            *(const float4*)(Bb + (size_t)(k0 + brow) * N + bcol);
        __syncthreads();

        #pragma unroll
        for (int kk = 0; kk < 8; kk++) {
            float a[8], b[8];
            *(float4*)&a[0] = *(const float4*)&As[kk][ty * 8];
            *(float4*)&a[4] = *(const float4*)&As[kk][ty * 8 + 4];
            *(float4*)&b[0] = *(const float4*)&Bs[kk][tx * 8];
            *(float4*)&b[4] = *(const float4*)&Bs[kk][tx * 8 + 4];
            #pragma unroll
            for (int i = 0; i < 8; i++)
                #pragma unroll
                for (int j = 0; j < 8; j++)
                    acc[i][j] = fmaf(a[i], b[j], acc[i][j]);
        }
        __syncthreads();
    }

    float* Cb = C + (size_t)(by * 128 + ty * 8) * N + bx * 128 + tx * 8;
    #pragma unroll
    for (int i = 0; i < 8; i++) {
        *(float4*)(Cb + (size_t)i * N) =
            make_float4(acc[i][0], acc[i][1], acc[i][2], acc[i][3]);
        *(float4*)(Cb + (size_t)i * N + 4) =
            make_float4(acc[i][4], acc[i][5], acc[i][6], acc[i][7]);
    }
}

// ---------------------------------------------------------------------------
// RoPE in-place on g_q and g_k
// ---------------------------------------------------------------------------
__global__ __launch_bounds__(256)
void rope_kernel() {
    const int totq = BB * TT * NH * 64;
    const int totk = BB * TT * NKV * 64;
    int idx = blockIdx.x * blockDim.x + threadIdx.x;
    if (idx < totq) {
        int d  = idx & 63;
        int h  = (idx >> 6) % NH;
        int bt = idx / (64 * NH);
        int t  = bt & (TT - 1);
        float inv = (float)pow(10000.0, -(double)d / 64.0);
        float ang = (float)t * inv;
        float s, c;
        sincosf(ang, &s, &c);
        float* p = g_q + (size_t)bt * (NH * HDIM) + h * HDIM;
        float x1 = p[d], x2 = p[d + 64];
        p[d]      = x1 * c - x2 * s;
        p[d + 64] = x2 * c + x1 * s;
    } else if (idx < totq + totk) {
        int j  = idx - totq;
        int d  = j & 63;
        int h  = (j >> 6) % NKV;
        int bt = j / (64 * NKV);
        int t  = bt & (TT - 1);
        float inv = (float)pow(10000.0, -(double)d / 64.0);
        float ang = (float)t * inv;
        float s, c;
        sincosf(ang, &s, &c);
        float* p = g_k + (size_t)bt * (NKV * HDIM) + h * HDIM;
        float x1 = p[d], x2 = p[d + 64];
        p[d]      = x1 * c - x2 * s;
        p[d + 64] = x2 * c + x1 * s;
    }
}

// ---------------------------------------------------------------------------
// Flash attention, fp32, BM=BN=64, HD=128, GQA (4 q heads per kv head)
// smem layout (floats):
//   Qs [128][68] transposed : 0      .. 8704
//   Ks [128][68] transposed : 8704   .. 17408
//   Vs [64][128]            : 17408  .. 25600
//   Ss [64][65]             : 25600  .. 29760
//   rowScale[64]            : 29760
//   rowL[64]                : 29824
//   maskS[64] (int)         : 29888
// total 29952 floats = 119808 bytes
// ---------------------------------------------------------------------------
#define ATTN_SMEM_BYTES (29952 * 4)

__global__ __launch_bounds__(256, 1)
void attn_kernel(const int* __restrict__ mask, const int* __restrict__ causal_p) {
    extern __shared__ float sm[];
    float* Qs       = sm;
    float* Ks       = sm + 8704;
    float* Vs       = sm + 17408;
    float* Ss       = sm + 25600;
    float* rowScale = sm + 29760;
    float* rowL     = sm + 29824;
    int*   maskS    = (int*)(sm + 29888);

    const int tid = threadIdx.x;
    const int tx = tid & 15;
    const int ty = tid >> 4;
    const int qb = blockIdx.x;   // query block (64 rows)
    const int h  = blockIdx.y;   // q head
    const int b  = blockIdx.z;
    const int kvh = h >> 2;      // kv head = h / (H/HKV)
    const int causal = causal_p[0];

    const float scale = 0.08838834764831845f;  // 1/sqrt(128)

    // Load Q tile, transposed, pre-scaled
    const float* qbase = g_q + ((size_t)b * TT + qb * 64) * (NH * HDIM) + h * HDIM;
    #pragma unroll
    for (int it = 0; it < 8; it++) {
        int task = tid + 256 * it;
        int d  = task & 127;
        int q0 = (task >> 7) << 2;
        float4 v;
        v.x = qbase[(size_t)(q0 + 0) * 2048 + d] * scale;
        v.y = qbase[(size_t)(q0 + 1) * 2048 + d] * scale;
        v.z = qbase[(size_t)(q0 + 2) * 2048 + d] * scale;
        v.w = qbase[(size_t)(q0 + 3) * 2048 + d] * scale;
        *(float4*)&Qs[d * 68 + q0] = v;
    }

    float accO[4][8];
    #pragma unroll
    for (int i = 0; i < 4; i++)
        #pragma unroll
        for (int j = 0; j < 8; j++) accO[i][j] = 0.0f;

    float m_r = -1e30f, l_r = 0.0f;  // valid in threads tid<64 (row = tid)

    const float* kbase = g_k + (size_t)b * TT * (NKV * HDIM) + kvh * HDIM;
    const float* vbase = g_v + (size_t)b * TT * (NKV * HDIM) + kvh * HDIM;
    const int kbmax = causal ? qb : (TT / 64 - 1);

    for (int kb = 0; kb <= kbmax; kb++) {
        const int kr0 = kb * 64;

        // K tile transposed
        #pragma unroll
        for (int it = 0; it < 8; it++) {
            int task = tid + 256 * it;
            int d  = task & 127;
            int k0 = (task >> 7) << 2;
            float4 v;
            v.x = kbase[(size_t)(kr0 + k0 + 0) * 512 + d];
            v.y = kbase[(size_t)(kr0 + k0 + 1) * 512 + d];
            v.z = kbase[(size_t)(kr0 + k0 + 2) * 512 + d];
            v.w = kbase[(size_t)(kr0 + k0 + 3) * 512 + d];
            *(float4*)&Ks[d * 68 + k0] = v;
        }
        // V tile natural
        #pragma unroll
        for (int it = 0; it < 8; it++) {
            int f = tid + 256 * it;
            int r = f >> 5;
            int c = (f & 31) << 2;
            *(float4*)&Vs[r * 128 + c] =
                *(const float4*)&vbase[(size_t)(kr0 + r) * 512 + c];
        }
        if (tid < 64) maskS[tid] = mask[b * TT + kr0 + tid];
        __syncthreads();

        // S = Q @ K^T (already scaled)
        float s[4][4];
        #pragma unroll
        for (int i = 0; i < 4; i++)
            #pragma unroll
            for (int j = 0; j < 4; j++) s[i][j] = 0.0f;

        #pragma unroll 8
        for (int kk = 0; kk < 128; kk++) {
            float a[4], bb[4];
            *(float4*)a  = *(const float4*)&Qs[kk * 68 + ty * 4];
            *(float4*)bb = *(const float4*)&Ks[kk * 68 + tx * 4];
            #pragma unroll
            for (int i = 0; i < 4; i++)
                #pragma unroll
                for (int j = 0; j < 4; j++)
                    s[i][j] = fmaf(a[i], bb[j], s[i][j]);
        }

        // mask + store to smem
        const int qg0 = qb * 64 + ty * 4;
        const int kg0 = kr0 + tx * 4;
        #pragma unroll
        for (int i = 0; i < 4; i++)
            #pragma unroll
            for (int j = 0; j < 4; j++) {
                bool bad = (maskS[tx * 4 + j] == 0) ||
                           (causal && (kg0 + j > qg0 + i));
                Ss[(ty * 4 + i) * 65 + tx * 4 + j] = bad ? -1e30f : s[i][j];
            }
        __syncthreads();

        // online softmax, one thread per row
        if (tid < 64) {
            float* row = &Ss[tid * 65];
            float mb = -1e30f;
            #pragma unroll 8
            for (int k = 0; k < 64; k++) mb = fmaxf(mb, row[k]);
            float mnew = fmaxf(m_r, mb);
            float sc = __expf(m_r - mnew);
            float ls = 0.0f;
            #pragma unroll 8
            for (int k = 0; k < 64; k++) {
                float p = __expf(row[k] - mnew);
                row[k] = p;
                ls += p;
            }
            l_r = l_r * sc + ls;
            m_r = mnew;
            rowScale[tid] = sc;
        }
        __syncthreads();

        // rescale accumulators
        float f0 = rowScale[ty * 4 + 0];
        float f1 = rowScale[ty * 4 + 1];
        float f2 = rowScale[ty * 4 + 2];
        float f3 = rowScale[ty * 4 + 3];
        #pragma unroll
        for (int j = 0; j < 8; j++) {
            accO[0][j] *= f0; accO[1][j] *= f1;
            accO[2][j] *= f2; accO[3][j] *= f3;
        }

        // O += P @ V
        #pragma unroll 4
        for (int kk = 0; kk < 64; kk++) {
            float p[4];
            p[0] = Ss[(ty * 4 + 0) * 65 + kk];
            p[1] = Ss[(ty * 4 + 1) * 65 + kk];
            p[2] = Ss[(ty * 4 + 2) * 65 + kk];
            p[3] = Ss[(ty * 4 + 3) * 65 + kk];
            float vv[8];
            *(float4*)&vv[0] = *(const float4*)&Vs[kk * 128 + tx * 8];
            *(float4*)&vv[4] = *(const float4*)&Vs[kk * 128 + tx * 8 + 4];
            #pragma unroll
            for (int i = 0; i < 4; i++)
                #pragma unroll
                for (int j = 0; j < 8; j++)
                    accO[i][j] = fmaf(p[i], vv[j], accO[i][j]);
        }
        __syncthreads();
    }

    if (tid < 64) rowL[tid] = l_r;
    __syncthreads();

    float invl[4];
    #pragma unroll
    for (int i = 0; i < 4; i++) invl[i] = 1.0f / rowL[ty * 4 + i];

    float* obase = g_o + ((size_t)b * TT + qb * 64 + ty * 4) * 2048 + h * HDIM + tx * 8;
    #pragma unroll
    for (int i = 0; i < 4; i++) {
        *(float4*)(obase + (size_t)i * 2048) =
            make_float4(accO[i][0] * invl[i], accO[i][1] * invl[i],
                        accO[i][2] * invl[i], accO[i][3] * invl[i]);
        *(float4*)(obase + (size_t)i * 2048 + 4) =
            make_float4(accO[i][4] * invl[i], accO[i][5] * invl[i],
                        accO[i][6] * invl[i], accO[i][7] * invl[i]);
    }
}

// ---------------------------------------------------------------------------
extern "C" void kernel_launch(void* const* d_in, const int* in_sizes, int n_in,
                              void* d_out, int out_size) {
    const float* x      = (const float*)d_in[0];
    const int*   mask   = (const int*)d_in[1];
    const int*   causal = (const int*)d_in[2];
    const float* wq     = (const float*)d_in[3];
    const float* wk     = (const float*)d_in[4];
    const float* wv     = (const float*)d_in[5];
    const float* wo     = (const float*)d_in[6];
    float* out = (float*)d_out;

    float *gq, *gk, *gv, *go;
    cudaGetSymbolAddress((void**)&gq, g_q);
    cudaGetSymbolAddress((void**)&gk, g_k);
    cudaGetSymbolAddress((void**)&gv, g_v);
    cudaGetSymbolAddress((void**)&go, g_o);

    const int M = BB * TT;  // 4096

    // QKV projections
    sgemm_kernel<<<dim3(DD / 128, M / 128), 256>>>(x, wq, gq, M, DD, DD);
    sgemm_kernel<<<dim3((NKV * HDIM) / 128, M / 128), 256>>>(x, wk, gk, M, NKV * HDIM, DD);
    sgemm_kernel<<<dim3((NKV * HDIM) / 128, M / 128), 256>>>(x, wv, gv, M, NKV * HDIM, DD);

    // RoPE
    int rope_threads = BB * TT * (NH + NKV) * 64;
    rope_kernel<<<(rope_threads + 255) / 256, 256>>>();

    // Attention
    cudaFuncSetAttribute(attn_kernel, cudaFuncAttributeMaxDynamicSharedMemorySize,
                         ATTN_SMEM_BYTES);
    attn_kernel<<<dim3(TT / 64, NH, BB), 256, ATTN_SMEM_BYTES>>>(mask, causal);

    // Output projection
    sgemm_kernel<<<dim3(DD / 128, M / 128), 256>>>(go, wo, out, M, DD, DD);
}

// round 2
// speedup vs baseline: 2.0561x; 2.0561x over previous
#include <cuda_runtime.h>
#include <math.h>
#include <stdint.h>

#define BB   2
#define TT   2048
#define DD   2048
#define NH   16
#define NKV  4
#define HDIM 128

// Scratch (allocation-free rule: __device__ globals)
__device__ float g_q[BB*TT*NH*HDIM];    // [B*T, 2048]
__device__ float g_k[BB*TT*NKV*HDIM];   // [B*T, 512]
__device__ float g_v[BB*TT*NKV*HDIM];   // [B*T, 512]
__device__ float g_o[BB*TT*NH*HDIM];    // [B*T, 2048]

// ---------------------------------------------------------------------------
// TF32 tensor-core GEMM: C[M,N] = A[M,K] @ B[K,N], row-major.
// BM=128, BN=128, BK=32, 256 threads (8 warps), warp tile 64x32,
// mma.sync.aligned.m16n8k8.row.col.f32.tf32.tf32.f32
// smem pitches: As pitch 36 (4g+tig banks distinct), Bs pitch 136 (8tig+g).
// ---------------------------------------------------------------------------
#define APITCH 36
#define BPITCH 136

__device__ __forceinline__ uint32_t f32_to_tf32(float x) {
    uint32_t r;
    asm("cvt.rna.tf32.f32 %0, %1;" : "=r"(r) : "f"(x));
    return r;
}

__global__ __launch_bounds__(256, 2)
void tf32_gemm_kernel(const float* __restrict__ A, const float* __restrict__ B,
                      float* __restrict__ C, int M, int N, int K) {
    __shared__ uint32_t As[128 * APITCH];
    __shared__ uint32_t Bs[32 * BPITCH];

    const int tid  = threadIdx.x;
    const int wid  = tid >> 5;
    const int lane = tid & 31;
    const int g    = lane >> 2;   // group id 0..7
    const int tig  = lane & 3;    // thread in group 0..3

    const int warp_m = (wid & 1) * 64;   // 0 or 64
    const int warp_n = (wid >> 1) * 32;  // 0,32,64,96

    const int bx = blockIdx.x;
    const int by = blockIdx.y;

    const float* Ab = A + (size_t)by * 128 * K;
    const float* Bb = B + (size_t)bx * 128;

    float acc[4][4][4];
    #pragma unroll
    for (int i = 0; i < 4; i++)
        #pragma unroll
        for (int j = 0; j < 4; j++)
            #pragma unroll
            for (int c = 0; c < 4; c++) acc[i][j][c] = 0.0f;

    // global-load task decomposition
    const int a_row = tid >> 1;           // 0..127 (two threads per row)
    const int a_c4  = (tid & 1) << 4;     // col offset 0 or 16 (x4 floats => 4 f4 each)
    const int b_kr  = tid >> 5;           // 0..7 (x4 rows)
    const int b_c4  = (lane) << 2;        // 0..124

    for (int k0 = 0; k0 < K; k0 += 32) {
        // ---- load A tile 128x32: each thread 4 float4 (one row half) ----
        {
            const float* src = Ab + (size_t)a_row * K + k0 + a_c4;
            uint32_t* dst = &As[a_row * APITCH + a_c4];
            #pragma unroll
            for (int v = 0; v < 4; v++) {
                float4 f = *(const float4*)(src + v * 4);
                dst[v * 4 + 0] = f32_to_tf32(f.x);
                dst[v * 4 + 1] = f32_to_tf32(f.y);
                dst[v * 4 + 2] = f32_to_tf32(f.z);
                dst[v * 4 + 3] = f32_to_tf32(f.w);
            }
        }
        // ---- load B tile 32x128: each thread 4 rows of one float4 ----
        {
            #pragma unroll
            for (int v = 0; v < 4; v++) {
                int kr = b_kr + v * 8;
                float4 f = *(const float4*)(Bb + (size_t)(k0 + kr) * N + b_c4);
                uint32_t* dst = &Bs[kr * BPITCH + b_c4];
                dst[0] = f32_to_tf32(f.x);
                dst[1] = f32_to_tf32(f.y);
                dst[2] = f32_to_tf32(f.z);
                dst[3] = f32_to_tf32(f.w);
            }
        }
        __syncthreads();

        #pragma unroll
        for (int ks = 0; ks < 4; ks++) {
            const int kk = ks * 8;
            uint32_t af[4][4];
            #pragma unroll
            for (int mt = 0; mt < 4; mt++) {
                int ar = warp_m + mt * 16 + g;
                af[mt][0] = As[ar * APITCH + kk + tig];
                af[mt][1] = As[(ar + 8) * APITCH + kk + tig];
                af[mt][2] = As[ar * APITCH + kk + tig + 4];
                af[mt][3] = As[(ar + 8) * APITCH + kk + tig + 4];
            }
            uint32_t bf[4][2];
            #pragma unroll
            for (int nt = 0; nt < 4; nt++) {
                int bc = warp_n + nt * 8 + g;
                bf[nt][0] = Bs[(kk + tig) * BPITCH + bc];
                bf[nt][1] = Bs[(kk + tig + 4) * BPITCH + bc];
            }
            #pragma unroll
            for (int mt = 0; mt < 4; mt++)
                #pragma unroll
                for (int nt = 0; nt < 4; nt++) {
                    asm volatile(
                        "mma.sync.aligned.m16n8k8.row.col.f32.tf32.tf32.f32 "
                        "{%0,%1,%2,%3}, {%4,%5,%6,%7}, {%8,%9}, {%0,%1,%2,%3};\n"
                        : "+f"(acc[mt][nt][0]), "+f"(acc[mt][nt][1]),
                          "+f"(acc[mt][nt][2]), "+f"(acc[mt][nt][3])
                        : "r"(af[mt][0]), "r"(af[mt][1]),
                          "r"(af[mt][2]), "r"(af[mt][3]),
                          "r"(bf[nt][0]), "r"(bf[nt][1]));
                }
        }
        __syncthreads();
    }

    // epilogue
    float* Cw = C + (size_t)(by * 128 + warp_m) * N + bx * 128 + warp_n;
    #pragma unroll
    for (int mt = 0; mt < 4; mt++) {
        #pragma unroll
        for (int nt = 0; nt < 4; nt++) {
            int row = mt * 16 + g;
            int col = nt * 8 + 2 * tig;
            *(float2*)(Cw + (size_t)row * N + col) =
                make_float2(acc[mt][nt][0], acc[mt][nt][1]);
            *(float2*)(Cw + (size_t)(row + 8) * N + col) =
                make_float2(acc[mt][nt][2], acc[mt][nt][3]);
        }
    }
}

// ---------------------------------------------------------------------------
// RoPE in-place on g_q and g_k (pure fp32 math; no fp64!)
// ---------------------------------------------------------------------------
#define LOG2_THETA_OVER_HALF 0.20762050593046128f   // log2(10000)/64

__global__ __launch_bounds__(256)
void rope_kernel() {
    const int totq = BB * TT * NH * 64;
    const int totk = BB * TT * NKV * 64;
    int idx = blockIdx.x * blockDim.x + threadIdx.x;
    if (idx < totq) {
        int d  = idx & 63;
        int h  = (idx >> 6) % NH;
        int bt = idx / (64 * NH);
        int t  = bt & (TT - 1);
        float inv = exp2f(-(float)d * LOG2_THETA_OVER_HALF);
        float ang = (float)t * inv;
        float s, c;
        sincosf(ang, &s, &c);
        float* p = g_q + (size_t)bt * (NH * HDIM) + h * HDIM;
        float x1 = p[d], x2 = p[d + 64];
        p[d]      = x1 * c - x2 * s;
        p[d + 64] = x2 * c + x1 * s;
    } else if (idx < totq + totk) {
        int j  = idx - totq;
        int d  = j & 63;
        int h  = (j >> 6) % NKV;
        int bt = j / (64 * NKV);
        int t  = bt & (TT - 1);
        float inv = exp2f(-(float)d * LOG2_THETA_OVER_HALF);
        float ang = (float)t * inv;
        float s, c;
        sincosf(ang, &s, &c);
        float* p = g_k + (size_t)bt * (NKV * HDIM) + h * HDIM;
        float x1 = p[d], x2 = p[d + 64];
        p[d]      = x1 * c - x2 * s;
        p[d + 64] = x2 * c + x1 * s;
    }
}

// ---------------------------------------------------------------------------
// Flash attention, fp32, BM=BN=64, HD=128, GQA (4 q heads per kv head)
// ---------------------------------------------------------------------------
#define ATTN_SMEM_BYTES (29952 * 4)

__global__ __launch_bounds__(256, 1)
void attn_kernel(const int* __restrict__ mask, const int* __restrict__ causal_p) {
    extern __shared__ float sm[];
    float* Qs       = sm;
    float* Ks       = sm + 8704;
    float* Vs       = sm + 17408;
    float* Ss       = sm + 25600;
    float* rowScale = sm + 29760;
    float* rowL     = sm + 29824;
    int*   maskS    = (int*)(sm + 29888);

    const int tid = threadIdx.x;
    const int tx = tid & 15;
    const int ty = tid >> 4;
    const int qb = blockIdx.x;
    const int h  = blockIdx.y;
    const int b  = blockIdx.z;
    const int kvh = h >> 2;
    const int causal = causal_p[0];

    const float scale = 0.08838834764831845f;  // 1/sqrt(128)

    const float* qbase = g_q + ((size_t)b * TT + qb * 64) * (NH * HDIM) + h * HDIM;
    #pragma unroll
    for (int it = 0; it < 8; it++) {
        int task = tid + 256 * it;
        int d  = task & 127;
        int q0 = (task >> 7) << 2;
        float4 v;
        v.x = qbase[(size_t)(q0 + 0) * 2048 + d] * scale;
        v.y = qbase[(size_t)(q0 + 1) * 2048 + d] * scale;
        v.z = qbase[(size_t)(q0 + 2) * 2048 + d] * scale;
        v.w = qbase[(size_t)(q0 + 3) * 2048 + d] * scale;
        *(float4*)&Qs[d * 68 + q0] = v;
    }

    float accO[4][8];
    #pragma unroll
    for (int i = 0; i < 4; i++)
        #pragma unroll
        for (int j = 0; j < 8; j++) accO[i][j] = 0.0f;

    float m_r = -1e30f, l_r = 0.0f;

    const float* kbase = g_k + (size_t)b * TT * (NKV * HDIM) + kvh * HDIM;
    const float* vbase = g_v + (size_t)b * TT * (NKV * HDIM) + kvh * HDIM;
    const int kbmax = causal ? qb : (TT / 64 - 1);

    for (int kb = 0; kb <= kbmax; kb++) {
        const int kr0 = kb * 64;

        #pragma unroll
        for (int it = 0; it < 8; it++) {
            int task = tid + 256 * it;
            int d  = task & 127;
            int k0 = (task >> 7) << 2;
            float4 v;
            v.x = kbase[(size_t)(kr0 + k0 + 0) * 512 + d];
            v.y = kbase[(size_t)(kr0 + k0 + 1) * 512 + d];
            v.z = kbase[(size_t)(kr0 + k0 + 2) * 512 + d];
            v.w = kbase[(size_t)(kr0 + k0 + 3) * 512 + d];
            *(float4*)&Ks[d * 68 + k0] = v;
        }
        #pragma unroll
        for (int it = 0; it < 8; it++) {
            int f = tid + 256 * it;
            int r = f >> 5;
            int c = (f & 31) << 2;
            *(float4*)&Vs[r * 128 + c] =
                *(const float4*)&vbase[(size_t)(kr0 + r) * 512 + c];
        }
        if (tid < 64) maskS[tid] = mask[b * TT + kr0 + tid];
        __syncthreads();

        float s[4][4];
        #pragma unroll
        for (int i = 0; i < 4; i++)
            #pragma unroll
            for (int j = 0; j < 4; j++) s[i][j] = 0.0f;

        #pragma unroll 8
        for (int kk = 0; kk < 128; kk++) {
            float a[4], bb[4];
            *(float4*)a  = *(const float4*)&Qs[kk * 68 + ty * 4];
            *(float4*)bb = *(const float4*)&Ks[kk * 68 + tx * 4];
            #pragma unroll
            for (int i = 0; i < 4; i++)
                #pragma unroll
                for (int j = 0; j < 4; j++)
                    s[i][j] = fmaf(a[i], bb[j], s[i][j]);
        }

        const int qg0 = qb * 64 + ty * 4;
        const int kg0 = kr0 + tx * 4;
        #pragma unroll
        for (int i = 0; i < 4; i++)
            #pragma unroll
            for (int j = 0; j < 4; j++) {
                bool bad = (maskS[tx * 4 + j] == 0) ||
                           (causal && (kg0 + j > qg0 + i));
                Ss[(ty * 4 + i) * 65 + tx * 4 + j] = bad ? -1e30f : s[i][j];
            }
        __syncthreads();

        if (tid < 64) {
            float* row = &Ss[tid * 65];
            float mb = -1e30f;
            #pragma unroll 8
            for (int k = 0; k < 64; k++) mb = fmaxf(mb, row[k]);
            float mnew = fmaxf(m_r, mb);
            float sc = __expf(m_r - mnew);
            float ls = 0.0f;
            #pragma unroll 8
            for (int k = 0; k < 64; k++) {
                float p = __expf(row[k] - mnew);
                row[k] = p;
                ls += p;
            }
            l_r = l_r * sc + ls;
            m_r = mnew;
            rowScale[tid] = sc;
        }
        __syncthreads();

        float f0 = rowScale[ty * 4 + 0];
        float f1 = rowScale[ty * 4 + 1];
        float f2 = rowScale[ty * 4 + 2];
        float f3 = rowScale[ty * 4 + 3];
        #pragma unroll
        for (int j = 0; j < 8; j++) {
            accO[0][j] *= f0; accO[1][j] *= f1;
            accO[2][j] *= f2; accO[3][j] *= f3;
        }

        #pragma unroll 4
        for (int kk = 0; kk < 64; kk++) {
            float p[4];
            p[0] = Ss[(ty * 4 + 0) * 65 + kk];
            p[1] = Ss[(ty * 4 + 1) * 65 + kk];
            p[2] = Ss[(ty * 4 + 2) * 65 + kk];
            p[3] = Ss[(ty * 4 + 3) * 65 + kk];
            float vv[8];
            *(float4*)&vv[0] = *(const float4*)&Vs[kk * 128 + tx * 8];
            *(float4*)&vv[4] = *(const float4*)&Vs[kk * 128 + tx * 8 + 4];
            #pragma unroll
            for (int i = 0; i < 4; i++)
                #pragma unroll
                for (int j = 0; j < 8; j++)
                    accO[i][j] = fmaf(p[i], vv[j], accO[i][j]);
        }
        __syncthreads();
    }

    if (tid < 64) rowL[tid] = l_r;
    __syncthreads();

    float invl[4];
    #pragma unroll
    for (int i = 0; i < 4; i++) invl[i] = 1.0f / rowL[ty * 4 + i];

    float* obase = g_o + ((size_t)b * TT + qb * 64 + ty * 4) * 2048 + h * HDIM + tx * 8;
    #pragma unroll
    for (int i = 0; i < 4; i++) {
        *(float4*)(obase + (size_t)i * 2048) =
            make_float4(accO[i][0] * invl[i], accO[i][1] * invl[i],
                        accO[i][2] * invl[i], accO[i][3] * invl[i]);
        *(float4*)(obase + (size_t)i * 2048 + 4) =
            make_float4(accO[i][4] * invl[i], accO[i][5] * invl[i],
                        accO[i][6] * invl[i], accO[i][7] * invl[i]);
    }
}

// ---------------------------------------------------------------------------
extern "C" void kernel_launch(void* const* d_in, const int* in_sizes, int n_in,
                              void* d_out, int out_size) {
    const float* x      = (const float*)d_in[0];
    const int*   mask   = (const int*)d_in[1];
    const int*   causal = (const int*)d_in[2];
    const float* wq     = (const float*)d_in[3];
    const float* wk     = (const float*)d_in[4];
    const float* wv     = (const float*)d_in[5];
    const float* wo     = (const float*)d_in[6];
    float* out = (float*)d_out;

    float *gq, *gk, *gv, *go;
    cudaGetSymbolAddress((void**)&gq, g_q);
    cudaGetSymbolAddress((void**)&gk, g_k);
    cudaGetSymbolAddress((void**)&gv, g_v);
    cudaGetSymbolAddress((void**)&go, g_o);

    const int M = BB * TT;  // 4096

    // QKV projections (tf32 tensor cores)
    tf32_gemm_kernel<<<dim3(DD / 128, M / 128), 256>>>(x, wq, gq, M, DD, DD);
    tf32_gemm_kernel<<<dim3((NKV * HDIM) / 128, M / 128), 256>>>(x, wk, gk, M, NKV * HDIM, DD);
    tf32_gemm_kernel<<<dim3((NKV * HDIM) / 128, M / 128), 256>>>(x, wv, gv, M, NKV * HDIM, DD);

    // RoPE
    int rope_threads = BB * TT * (NH + NKV) * 64;
    rope_kernel<<<(rope_threads + 255) / 256, 256>>>();

    // Attention
    cudaFuncSetAttribute(attn_kernel, cudaFuncAttributeMaxDynamicSharedMemorySize,
                         ATTN_SMEM_BYTES);
    attn_kernel<<<dim3(TT / 64, NH, BB), 256, ATTN_SMEM_BYTES>>>(mask, causal);

    // Output projection (tf32 tensor cores)
    tf32_gemm_kernel<<<dim3(DD / 128, M / 128), 256>>>(go, wo, out, M, DD, DD);
}

// round 3
// speedup vs baseline: 3.3321x; 1.6206x over previous
#include <cuda_runtime.h>
#include <math.h>
#include <stdint.h>

#define BB   2
#define TT   2048
#define DD   2048
#define NH   16
#define NKV  4
#define HDIM 128

// Scratch (allocation-free rule: __device__ globals)
__device__ float g_q[BB*TT*NH*HDIM];    // [B*T, 2048]
__device__ float g_k[BB*TT*NKV*HDIM];   // [B*T, 512]
__device__ float g_v[BB*TT*NKV*HDIM];   // [B*T, 512]
__device__ float g_o[BB*TT*NH*HDIM];    // [B*T, 2048]

__device__ __forceinline__ uint32_t f32_to_tf32(float x) {
    uint32_t r;
    asm("cvt.rna.tf32.f32 %0, %1;" : "=r"(r) : "f"(x));
    return r;
}

__device__ __forceinline__ void mma_tf32(float c[4],
                                         uint32_t a0, uint32_t a1, uint32_t a2, uint32_t a3,
                                         uint32_t b0, uint32_t b1) {
    asm volatile(
        "mma.sync.aligned.m16n8k8.row.col.f32.tf32.tf32.f32 "
        "{%0,%1,%2,%3}, {%4,%5,%6,%7}, {%8,%9}, {%0,%1,%2,%3};\n"
        : "+f"(c[0]), "+f"(c[1]), "+f"(c[2]), "+f"(c[3])
        : "r"(a0), "r"(a1), "r"(a2), "r"(a3), "r"(b0), "r"(b1));
}

// ---------------------------------------------------------------------------
// TF32 tensor-core GEMM: C[M,N] = A[M,K] @ B[K,N], row-major. (unchanged)
// ---------------------------------------------------------------------------
#define APITCH 36
#define BPITCH 136

__global__ __launch_bounds__(256, 2)
void tf32_gemm_kernel(const float* __restrict__ A, const float* __restrict__ B,
                      float* __restrict__ C, int M, int N, int K) {
    __shared__ uint32_t As[128 * APITCH];
    __shared__ uint32_t Bs[32 * BPITCH];

    const int tid  = threadIdx.x;
    const int wid  = tid >> 5;
    const int lane = tid & 31;
    const int g    = lane >> 2;
    const int tig  = lane & 3;

    const int warp_m = (wid & 1) * 64;
    const int warp_n = (wid >> 1) * 32;

    const int bx = blockIdx.x;
    const int by = blockIdx.y;

    const float* Ab = A + (size_t)by * 128 * K;
    const float* Bb = B + (size_t)bx * 128;

    float acc[4][4][4];
    #pragma unroll
    for (int i = 0; i < 4; i++)
        #pragma unroll
        for (int j = 0; j < 4; j++)
            #pragma unroll
            for (int c = 0; c < 4; c++) acc[i][j][c] = 0.0f;

    const int a_row = tid >> 1;
    const int a_c4  = (tid & 1) << 4;
    const int b_kr  = tid >> 5;
    const int b_c4  = (lane) << 2;

    for (int k0 = 0; k0 < K; k0 += 32) {
        {
            const float* src = Ab + (size_t)a_row * K + k0 + a_c4;
            uint32_t* dst = &As[a_row * APITCH + a_c4];
            #pragma unroll
            for (int v = 0; v < 4; v++) {
                float4 f = *(const float4*)(src + v * 4);
                dst[v * 4 + 0] = f32_to_tf32(f.x);
                dst[v * 4 + 1] = f32_to_tf32(f.y);
                dst[v * 4 + 2] = f32_to_tf32(f.z);
                dst[v * 4 + 3] = f32_to_tf32(f.w);
            }
        }
        {
            #pragma unroll
            for (int v = 0; v < 4; v++) {
                int kr = b_kr + v * 8;
                float4 f = *(const float4*)(Bb + (size_t)(k0 + kr) * N + b_c4);
                uint32_t* dst = &Bs[kr * BPITCH + b_c4];
                dst[0] = f32_to_tf32(f.x);
                dst[1] = f32_to_tf32(f.y);
                dst[2] = f32_to_tf32(f.z);
                dst[3] = f32_to_tf32(f.w);
            }
        }
        __syncthreads();

        #pragma unroll
        for (int ks = 0; ks < 4; ks++) {
            const int kk = ks * 8;
            uint32_t af[4][4];
            #pragma unroll
            for (int mt = 0; mt < 4; mt++) {
                int ar = warp_m + mt * 16 + g;
                af[mt][0] = As[ar * APITCH + kk + tig];
                af[mt][1] = As[(ar + 8) * APITCH + kk + tig];
                af[mt][2] = As[ar * APITCH + kk + tig + 4];
                af[mt][3] = As[(ar + 8) * APITCH + kk + tig + 4];
            }
            uint32_t bf[4][2];
            #pragma unroll
            for (int nt = 0; nt < 4; nt++) {
                int bc = warp_n + nt * 8 + g;
                bf[nt][0] = Bs[(kk + tig) * BPITCH + bc];
                bf[nt][1] = Bs[(kk + tig + 4) * BPITCH + bc];
            }
            #pragma unroll
            for (int mt = 0; mt < 4; mt++)
                #pragma unroll
                for (int nt = 0; nt < 4; nt++)
                    mma_tf32(acc[mt][nt], af[mt][0], af[mt][1], af[mt][2], af[mt][3],
                             bf[nt][0], bf[nt][1]);
        }
        __syncthreads();
    }

    float* Cw = C + (size_t)(by * 128 + warp_m) * N + bx * 128 + warp_n;
    #pragma unroll
    for (int mt = 0; mt < 4; mt++) {
        #pragma unroll
        for (int nt = 0; nt < 4; nt++) {
            int row = mt * 16 + g;
            int col = nt * 8 + 2 * tig;
            *(float2*)(Cw + (size_t)row * N + col) =
                make_float2(acc[mt][nt][0], acc[mt][nt][1]);
            *(float2*)(Cw + (size_t)(row + 8) * N + col) =
                make_float2(acc[mt][nt][2], acc[mt][nt][3]);
        }
    }
}

// ---------------------------------------------------------------------------
// RoPE in-place on g_q and g_k (pure fp32 math)
// ---------------------------------------------------------------------------
#define LOG2_THETA_OVER_HALF 0.20762050593046128f   // log2(10000)/64

__global__ __launch_bounds__(256)
void rope_kernel() {
    const int totq = BB * TT * NH * 64;
    const int totk = BB * TT * NKV * 64;
    int idx = blockIdx.x * blockDim.x + threadIdx.x;
    if (idx < totq) {
        int d  = idx & 63;
        int h  = (idx >> 6) % NH;
        int bt = idx / (64 * NH);
        int t  = bt & (TT - 1);
        float inv = exp2f(-(float)d * LOG2_THETA_OVER_HALF);
        float ang = (float)t * inv;
        float s, c;
        sincosf(ang, &s, &c);
        float* p = g_q + (size_t)bt * (NH * HDIM) + h * HDIM;
        float x1 = p[d], x2 = p[d + 64];
        p[d]      = x1 * c - x2 * s;
        p[d + 64] = x2 * c + x1 * s;
    } else if (idx < totq + totk) {
        int j  = idx - totq;
        int d  = j & 63;
        int h  = (j >> 6) % NKV;
        int bt = j / (64 * NKV);
        int t  = bt & (TT - 1);
        float inv = exp2f(-(float)d * LOG2_THETA_OVER_HALF);
        float ang = (float)t * inv;
        float s, c;
        sincosf(ang, &s, &c);
        float* p = g_k + (size_t)bt * (NKV * HDIM) + h * HDIM;
        float x1 = p[d], x2 = p[d + 64];
        p[d]      = x1 * c - x2 * s;
        p[d + 64] = x2 * c + x1 * s;
    }
}

// ---------------------------------------------------------------------------
// Tensor-core flash attention (tf32 mma), BM=64, BN=64, HD=128.
// 256 threads = 8 warps: wm = wid&3 (m tile 16 rows), wn = wid>>2 (n half).
// smem (uint32 words):
//   Qs [64][136] : 0      (tf32, pre-scaled)
//   Ks [64][136] : 8704
//   Vs [64][136] : 17408
//   Ps [64][72]  : 26112  (tf32 probabilities)
//   redM float[2][64] : 30720
//   redS float[2][64] : 30848
//   maskS int[64]     : 30976
// total 31040 words = 124160 bytes
// ---------------------------------------------------------------------------
#define KP 136
#define PP 72
#define ATTN_SMEM_BYTES (31040 * 4)

__global__ __launch_bounds__(256, 1)
void attn_mma_kernel(const int* __restrict__ mask, const int* __restrict__ causal_p) {
    extern __shared__ uint32_t sm[];
    uint32_t* Qs   = sm;
    uint32_t* Ks   = sm + 8704;
    uint32_t* Vs   = sm + 17408;
    uint32_t* Ps   = sm + 26112;
    float*    redM = (float*)(sm + 30720);
    float*    redS = (float*)(sm + 30848);
    int*      maskS= (int*)(sm + 30976);

    const int tid  = threadIdx.x;
    const int wid  = tid >> 5;
    const int lane = tid & 31;
    const int g    = lane >> 2;
    const int tig  = lane & 3;
    const int wm   = wid & 3;
    const int wn   = wid >> 2;

    const int qb  = blockIdx.x;
    const int h   = blockIdx.y;
    const int b   = blockIdx.z;
    const int kvh = h >> 2;
    const int causal = causal_p[0];

    const float scale = 0.08838834764831845f;  // 1/sqrt(128)

    // ---- load Q tile (64 x 128) as tf32, pre-scaled ----
    {
        const float* qbase = g_q + ((size_t)b * TT + qb * 64) * 2048 + h * HDIM;
        #pragma unroll
        for (int it = 0; it < 8; it++) {
            int task = tid + 256 * it;
            int r = task >> 5;
            int c = (task & 31) << 2;
            float4 f = *(const float4*)(qbase + (size_t)r * 2048 + c);
            uint32_t* dst = &Qs[r * KP + c];
            dst[0] = f32_to_tf32(f.x * scale);
            dst[1] = f32_to_tf32(f.y * scale);
            dst[2] = f32_to_tf32(f.z * scale);
            dst[3] = f32_to_tf32(f.w * scale);
        }
    }

    const int r0 = 16 * wm + g;
    const int r1 = r0 + 8;
    const int qg0 = qb * 64 + r0;
    const int qg1 = qb * 64 + r1;

    float accO[8][4];
    #pragma unroll
    for (int nt = 0; nt < 8; nt++)
        #pragma unroll
        for (int c = 0; c < 4; c++) accO[nt][c] = 0.0f;

    float m0 = -1e30f, m1 = -1e30f, l0 = 0.0f, l1 = 0.0f;

    const float* kbase = g_k + (size_t)b * TT * 512 + kvh * HDIM;
    const float* vbase = g_v + (size_t)b * TT * 512 + kvh * HDIM;
    const int kbmax = causal ? qb : (TT / 64 - 1);

    for (int kb = 0; kb <= kbmax; kb++) {
        const int kr0 = kb * 64;

        __syncthreads();   // previous iteration consumers done

        // ---- load K and V tiles (64 x 128 each) as tf32 ----
        #pragma unroll
        for (int it = 0; it < 8; it++) {
            int task = tid + 256 * it;
            int r = task >> 5;
            int c = (task & 31) << 2;
            float4 f = *(const float4*)(kbase + (size_t)(kr0 + r) * 512 + c);
            uint32_t* dst = &Ks[r * KP + c];
            dst[0] = f32_to_tf32(f.x);
            dst[1] = f32_to_tf32(f.y);
            dst[2] = f32_to_tf32(f.z);
            dst[3] = f32_to_tf32(f.w);
            float4 v = *(const float4*)(vbase + (size_t)(kr0 + r) * 512 + c);
            uint32_t* dvv = &Vs[r * KP + c];
            dvv[0] = f32_to_tf32(v.x);
            dvv[1] = f32_to_tf32(v.y);
            dvv[2] = f32_to_tf32(v.z);
            dvv[3] = f32_to_tf32(v.w);
        }
        if (tid < 64) maskS[tid] = mask[b * TT + kr0 + tid];
        __syncthreads();

        // ---- S = Q @ K^T (tf32 mma), warp computes 16x32 ----
        float sacc[4][4];
        #pragma unroll
        for (int nt = 0; nt < 4; nt++)
            #pragma unroll
            for (int c = 0; c < 4; c++) sacc[nt][c] = 0.0f;

        #pragma unroll
        for (int ks = 0; ks < 16; ks++) {
            const uint32_t* qr = &Qs[r0 * KP + ks * 8 + tig];
            uint32_t a0 = qr[0];
            uint32_t a2 = qr[4];
            uint32_t a1 = qr[8 * KP];
            uint32_t a3 = qr[8 * KP + 4];
            #pragma unroll
            for (int nt = 0; nt < 4; nt++) {
                const uint32_t* kr = &Ks[(32 * wn + 8 * nt + g) * KP + ks * 8 + tig];
                mma_tf32(sacc[nt], a0, a1, a2, a3, kr[0], kr[4]);
            }
        }

        // ---- mask + local row max ----
        float lm0 = -1e30f, lm1 = -1e30f;
        #pragma unroll
        for (int nt = 0; nt < 4; nt++) {
            #pragma unroll
            for (int e = 0; e < 2; e++) {
                int c  = 32 * wn + 8 * nt + 2 * tig + e;
                int kg = kr0 + c;
                bool mz = (maskS[c] == 0);
                if (mz || (causal && kg > qg0)) sacc[nt][e]     = -1e30f;
                if (mz || (causal && kg > qg1)) sacc[nt][e + 2] = -1e30f;
                lm0 = fmaxf(lm0, sacc[nt][e]);
                lm1 = fmaxf(lm1, sacc[nt][e + 2]);
            }
        }
        lm0 = fmaxf(lm0, __shfl_xor_sync(0xffffffffu, lm0, 1));
        lm0 = fmaxf(lm0, __shfl_xor_sync(0xffffffffu, lm0, 2));
        lm1 = fmaxf(lm1, __shfl_xor_sync(0xffffffffu, lm1, 1));
        lm1 = fmaxf(lm1, __shfl_xor_sync(0xffffffffu, lm1, 2));
        if (tig == 0) {
            redM[wn * 64 + r0] = lm0;
            redM[wn * 64 + r1] = lm1;
        }
        __syncthreads();

        float mn0 = fmaxf(m0, fmaxf(redM[r0], redM[64 + r0]));
        float mn1 = fmaxf(m1, fmaxf(redM[r1], redM[64 + r1]));
        float esc0 = __expf(m0 - mn0);
        float esc1 = __expf(m1 - mn1);

        // ---- p = exp(s - m), local row sums, write P to smem ----
        float ls0 = 0.0f, ls1 = 0.0f;
        #pragma unroll
        for (int nt = 0; nt < 4; nt++) {
            float p0 = __expf(sacc[nt][0] - mn0);
            float p1 = __expf(sacc[nt][1] - mn0);
            float p2 = __expf(sacc[nt][2] - mn1);
            float p3 = __expf(sacc[nt][3] - mn1);
            ls0 += p0 + p1;
            ls1 += p2 + p3;
            int c = 32 * wn + 8 * nt + 2 * tig;
            uint32_t* d0 = &Ps[r0 * PP + c];
            uint32_t* d1 = &Ps[r1 * PP + c];
            d0[0] = f32_to_tf32(p0);
            d0[1] = f32_to_tf32(p1);
            d1[0] = f32_to_tf32(p2);
            d1[1] = f32_to_tf32(p3);
        }
        ls0 += __shfl_xor_sync(0xffffffffu, ls0, 1);
        ls0 += __shfl_xor_sync(0xffffffffu, ls0, 2);
        ls1 += __shfl_xor_sync(0xffffffffu, ls1, 1);
        ls1 += __shfl_xor_sync(0xffffffffu, ls1, 2);
        if (tig == 0) {
            redS[wn * 64 + r0] = ls0;
            redS[wn * 64 + r1] = ls1;
        }

        // rescale accumulators
        #pragma unroll
        for (int nt = 0; nt < 8; nt++) {
            accO[nt][0] *= esc0; accO[nt][1] *= esc0;
            accO[nt][2] *= esc1; accO[nt][3] *= esc1;
        }
        __syncthreads();

        l0 = l0 * esc0 + redS[r0] + redS[64 + r0];
        l1 = l1 * esc1 + redS[r1] + redS[64 + r1];
        m0 = mn0;
        m1 = mn1;

        // ---- O += P @ V (tf32 mma), warp computes 16x64 ----
        #pragma unroll
        for (int ks = 0; ks < 8; ks++) {
            const uint32_t* pr = &Ps[r0 * PP + ks * 8 + tig];
            uint32_t a0 = pr[0];
            uint32_t a2 = pr[4];
            uint32_t a1 = pr[8 * PP];
            uint32_t a3 = pr[8 * PP + 4];
            #pragma unroll
            for (int nt = 0; nt < 8; nt++) {
                const uint32_t* vr = &Vs[(ks * 8 + tig) * KP + 64 * wn + 8 * nt + g];
                mma_tf32(accO[nt], a0, a1, a2, a3, vr[0], vr[4 * KP]);
            }
        }
    }

    // ---- epilogue: normalize and write ----
    float invl0 = 1.0f / l0;
    float invl1 = 1.0f / l1;
    float* ob0 = g_o + ((size_t)b * TT + qb * 64 + r0) * 2048 + h * HDIM + 64 * wn + 2 * tig;
    float* ob1 = g_o + ((size_t)b * TT + qb * 64 + r1) * 2048 + h * HDIM + 64 * wn + 2 * tig;
    #pragma unroll
    for (int nt = 0; nt < 8; nt++) {
        *(float2*)(ob0 + 8 * nt) = make_float2(accO[nt][0] * invl0, accO[nt][1] * invl0);
        *(float2*)(ob1 + 8 * nt) = make_float2(accO[nt][2] * invl1, accO[nt][3] * invl1);
    }
}

// ---------------------------------------------------------------------------
extern "C" void kernel_launch(void* const* d_in, const int* in_sizes, int n_in,
                              void* d_out, int out_size) {
    const float* x      = (const float*)d_in[0];
    const int*   mask   = (const int*)d_in[1];
    const int*   causal = (const int*)d_in[2];
    const float* wq     = (const float*)d_in[3];
    const float* wk     = (const float*)d_in[4];
    const float* wv     = (const float*)d_in[5];
    const float* wo     = (const float*)d_in[6];
    float* out = (float*)d_out;

    float *gq, *gk, *gv, *go;
    cudaGetSymbolAddress((void**)&gq, g_q);
    cudaGetSymbolAddress((void**)&gk, g_k);
    cudaGetSymbolAddress((void**)&gv, g_v);
    cudaGetSymbolAddress((void**)&go, g_o);

    const int M = BB * TT;  // 4096

    // QKV projections (tf32 tensor cores)
    tf32_gemm_kernel<<<dim3(DD / 128, M / 128), 256>>>(x, wq, gq, M, DD, DD);
    tf32_gemm_kernel<<<dim3((NKV * HDIM) / 128, M / 128), 256>>>(x, wk, gk, M, NKV * HDIM, DD);
    tf32_gemm_kernel<<<dim3((NKV * HDIM) / 128, M / 128), 256>>>(x, wv, gv, M, NKV * HDIM, DD);

    // RoPE
    int rope_threads = BB * TT * (NH + NKV) * 64;
    rope_kernel<<<(rope_threads + 255) / 256, 256>>>();

    // Attention (tensor cores)
    cudaFuncSetAttribute(attn_mma_kernel, cudaFuncAttributeMaxDynamicSharedMemorySize,
                         ATTN_SMEM_BYTES);
    attn_mma_kernel<<<dim3(TT / 64, NH, BB), 256, ATTN_SMEM_BYTES>>>(mask, causal);

    // Output projection (tf32 tensor cores)
    tf32_gemm_kernel<<<dim3(DD / 128, M / 128), 256>>>(go, wo, out, M, DD, DD);
}

// round 4
// speedup vs baseline: 3.6085x; 1.0829x over previous
#include <cuda_runtime.h>
#include <math.h>
#include <stdint.h>

#define BB   2
#define TT   2048
#define DD   2048
#define NH   16
#define NKV  4
#define HDIM 128

// Scratch (allocation-free rule: __device__ globals)
__device__ float g_q[BB*TT*NH*HDIM];    // [B*T, 2048]
__device__ float g_k[BB*TT*NKV*HDIM];   // [B*T, 512]
__device__ float g_v[BB*TT*NKV*HDIM];   // [B*T, 512]
__device__ float g_o[BB*TT*NH*HDIM];    // [B*T, 2048]

__device__ __forceinline__ uint32_t f32_to_tf32(float x) {
    uint32_t r;
    asm("cvt.rna.tf32.f32 %0, %1;" : "=r"(r) : "f"(x));
    return r;
}
__device__ __forceinline__ uint32_t ldcvt(const uint32_t* p) {
    return f32_to_tf32(__uint_as_float(*p));
}

__device__ __forceinline__ void mma_tf32(float c[4],
                                         uint32_t a0, uint32_t a1, uint32_t a2, uint32_t a3,
                                         uint32_t b0, uint32_t b1) {
    asm volatile(
        "mma.sync.aligned.m16n8k8.row.col.f32.tf32.tf32.f32 "
        "{%0,%1,%2,%3}, {%4,%5,%6,%7}, {%8,%9}, {%0,%1,%2,%3};\n"
        : "+f"(c[0]), "+f"(c[1]), "+f"(c[2]), "+f"(c[3])
        : "r"(a0), "r"(a1), "r"(a2), "r"(a3), "r"(b0), "r"(b1));
}

__device__ __forceinline__ void cp_async16(uint32_t smem_addr, const void* gptr) {
    asm volatile("cp.async.cg.shared.global [%0], [%1], 16;\n"
                 :: "r"(smem_addr), "l"(gptr));
}
__device__ __forceinline__ void cp_commit() {
    asm volatile("cp.async.commit_group;\n" ::: "memory");
}
template <int N>
__device__ __forceinline__ void cp_wait() {
    asm volatile("cp.async.wait_group %0;\n" :: "n"(N) : "memory");
}

// ---------------------------------------------------------------------------
// TF32 tensor-core GEMM body, cp.async double-buffered.
// BM=128, BN=128, BK=32, 256 threads, warp tile 64x32.
// smem stage (uint32 words): As 128*36=4608, Bs 32*136=4352 -> 8960 words.
// two stages -> 17920 words = 71680 bytes dynamic smem.
// ---------------------------------------------------------------------------
#define APITCH 36
#define BPITCH 136
#define ASZ    (128 * APITCH)
#define BSZ    (32 * BPITCH)
#define STG    (ASZ + BSZ)
#define GEMM_SMEM_BYTES (2 * STG * 4)

__device__ __forceinline__ void gemm_body(
    const float* __restrict__ A,   // [M,K] row-major, row block already applied
    const float* __restrict__ B,   // [K,N] row-major, col block already applied
    float* __restrict__ C,         // output at (row0, col0)
    int N, int K, uint32_t smem_base)
{
    const int tid  = threadIdx.x;
    const int wid  = tid >> 5;
    const int lane = tid & 31;
    const int g    = lane >> 2;
    const int tig  = lane & 3;

    const int warp_m = (wid & 1) * 64;
    const int warp_n = (wid >> 1) * 32;

    uint32_t* sm = (uint32_t*)__cvta_shared_to_generic(smem_base);

    const int a_row = tid >> 1;
    const int a_c4  = (tid & 1) << 4;
    const int b_kr  = tid >> 5;
    const int b_c4  = lane << 2;

    // byte addresses of stage bases in shared space
    const uint32_t aAddr = smem_base;                  // As of stage 0
    const uint32_t bAddr = smem_base + ASZ * 4;        // Bs of stage 0

    float acc[4][4][4];
    #pragma unroll
    for (int i = 0; i < 4; i++)
        #pragma unroll
        for (int j = 0; j < 4; j++)
            #pragma unroll
            for (int c = 0; c < 4; c++) acc[i][j][c] = 0.0f;

    const int niter = K >> 5;   // K/32

    // prefetch tile 0 into stage 0
    {
        const float* srcA = A + (size_t)a_row * K + a_c4;
        uint32_t dstA = aAddr + (a_row * APITCH + a_c4) * 4;
        #pragma unroll
        for (int v = 0; v < 4; v++)
            cp_async16(dstA + v * 16, srcA + v * 4);
        #pragma unroll
        for (int v = 0; v < 4; v++) {
            int kr = b_kr + v * 8;
            cp_async16(bAddr + (kr * BPITCH + b_c4) * 4,
                       B + (size_t)kr * N + b_c4);
        }
        cp_commit();
    }

    for (int i = 0; i < niter; i++) {
        const int cur = i & 1;
        if (i + 1 < niter) {
            const int nxt = cur ^ 1;
            const int k0 = (i + 1) << 5;
            const float* srcA = A + (size_t)a_row * K + k0 + a_c4;
            uint32_t dstA = aAddr + (nxt * STG + a_row * APITCH + a_c4) * 4;
            #pragma unroll
            for (int v = 0; v < 4; v++)
                cp_async16(dstA + v * 16, srcA + v * 4);
            #pragma unroll
            for (int v = 0; v < 4; v++) {
                int kr = b_kr + v * 8;
                cp_async16(bAddr + (nxt * STG + kr * BPITCH + b_c4) * 4,
                           B + (size_t)(k0 + kr) * N + b_c4);
            }
            cp_commit();
            cp_wait<1>();
        } else {
            cp_wait<0>();
        }
        __syncthreads();

        const uint32_t* As = sm + cur * STG;
        const uint32_t* Bs = As + ASZ;

        #pragma unroll
        for (int ks = 0; ks < 4; ks++) {
            const int kk = ks * 8;
            uint32_t af[4][4];
            #pragma unroll
            for (int mt = 0; mt < 4; mt++) {
                int ar = warp_m + mt * 16 + g;
                af[mt][0] = ldcvt(&As[ar * APITCH + kk + tig]);
                af[mt][1] = ldcvt(&As[(ar + 8) * APITCH + kk + tig]);
                af[mt][2] = ldcvt(&As[ar * APITCH + kk + tig + 4]);
                af[mt][3] = ldcvt(&As[(ar + 8) * APITCH + kk + tig + 4]);
            }
            uint32_t bf[4][2];
            #pragma unroll
            for (int nt = 0; nt < 4; nt++) {
                int bc = warp_n + nt * 8 + g;
                bf[nt][0] = ldcvt(&Bs[(kk + tig) * BPITCH + bc]);
                bf[nt][1] = ldcvt(&Bs[(kk + tig + 4) * BPITCH + bc]);
            }
            #pragma unroll
            for (int mt = 0; mt < 4; mt++)
                #pragma unroll
                for (int nt = 0; nt < 4; nt++)
                    mma_tf32(acc[mt][nt], af[mt][0], af[mt][1], af[mt][2], af[mt][3],
                             bf[nt][0], bf[nt][1]);
        }
        __syncthreads();
    }

    float* Cw = C + (size_t)warp_m * N + warp_n;
    #pragma unroll
    for (int mt = 0; mt < 4; mt++) {
        #pragma unroll
        for (int nt = 0; nt < 4; nt++) {
            int row = mt * 16 + g;
            int col = nt * 8 + 2 * tig;
            *(float2*)(Cw + (size_t)row * N + col) =
                make_float2(acc[mt][nt][0], acc[mt][nt][1]);
            *(float2*)(Cw + (size_t)(row + 8) * N + col) =
                make_float2(acc[mt][nt][2], acc[mt][nt][3]);
        }
    }
}

// Fused QKV projection: grid.x = 24 column tiles (16 q, 4 k, 4 v), grid.y = 32.
__global__ __launch_bounds__(256, 2)
void qkv_gemm_kernel(const float* __restrict__ x,
                     const float* __restrict__ wq, const float* __restrict__ wk,
                     const float* __restrict__ wv,
                     float* __restrict__ gq, float* __restrict__ gk,
                     float* __restrict__ gv) {
    extern __shared__ uint32_t smraw[];
    uint32_t smem_base = (uint32_t)__cvta_generic_to_shared(smraw);

    const int bx = blockIdx.x;
    const int by = blockIdx.y;

    const float* Bsel;
    float* Csel;
    int Nsel, colb;
    if (bx < 16)      { Bsel = wq; Csel = gq; Nsel = 2048; colb = bx * 128; }
    else if (bx < 20) { Bsel = wk; Csel = gk; Nsel = 512;  colb = (bx - 16) * 128; }
    else              { Bsel = wv; Csel = gv; Nsel = 512;  colb = (bx - 20) * 128; }

    gemm_body(x + (size_t)by * 128 * DD,
              Bsel + colb,
              Csel + (size_t)by * 128 * Nsel + colb,
              Nsel, DD, smem_base);
}

// Plain GEMM launcher (output projection): grid (N/128, M/128)
__global__ __launch_bounds__(256, 2)
void tf32_gemm_kernel(const float* __restrict__ A, const float* __restrict__ B,
                      float* __restrict__ C, int M, int N, int K) {
    extern __shared__ uint32_t smraw[];
    uint32_t smem_base = (uint32_t)__cvta_generic_to_shared(smraw);
    const int bx = blockIdx.x;
    const int by = blockIdx.y;
    gemm_body(A + (size_t)by * 128 * K,
              B + bx * 128,
              C + (size_t)by * 128 * N + bx * 128,
              N, K, smem_base);
}

// ---------------------------------------------------------------------------
// RoPE in-place on g_q and g_k (pure fp32 math)
// ---------------------------------------------------------------------------
#define LOG2_THETA_OVER_HALF 0.20762050593046128f   // log2(10000)/64

__global__ __launch_bounds__(256)
void rope_kernel() {
    const int totq = BB * TT * NH * 64;
    const int totk = BB * TT * NKV * 64;
    int idx = blockIdx.x * blockDim.x + threadIdx.x;
    if (idx < totq) {
        int d  = idx & 63;
        int h  = (idx >> 6) % NH;
        int bt = idx / (64 * NH);
        int t  = bt & (TT - 1);
        float inv = exp2f(-(float)d * LOG2_THETA_OVER_HALF);
        float ang = (float)t * inv;
        float s, c;
        sincosf(ang, &s, &c);
        float* p = g_q + (size_t)bt * (NH * HDIM) + h * HDIM;
        float x1 = p[d], x2 = p[d + 64];
        p[d]      = x1 * c - x2 * s;
        p[d + 64] = x2 * c + x1 * s;
    } else if (idx < totq + totk) {
        int j  = idx - totq;
        int d  = j & 63;
        int h  = (j >> 6) % NKV;
        int bt = j / (64 * NKV);
        int t  = bt & (TT - 1);
        float inv = exp2f(-(float)d * LOG2_THETA_OVER_HALF);
        float ang = (float)t * inv;
        float s, c;
        sincosf(ang, &s, &c);
        float* p = g_k + (size_t)bt * (NKV * HDIM) + h * HDIM;
        float x1 = p[d], x2 = p[d + 64];
        p[d]      = x1 * c - x2 * s;
        p[d + 64] = x2 * c + x1 * s;
    }
}

// ---------------------------------------------------------------------------
// Tensor-core flash attention (tf32 mma), BM=64, BN=64, HD=128. (unchanged)
// ---------------------------------------------------------------------------
#define KP 136
#define PP 72
#define ATTN_SMEM_BYTES (31040 * 4)

__global__ __launch_bounds__(256, 1)
void attn_mma_kernel(const int* __restrict__ mask, const int* __restrict__ causal_p) {
    extern __shared__ uint32_t sm[];
    uint32_t* Qs   = sm;
    uint32_t* Ks   = sm + 8704;
    uint32_t* Vs   = sm + 17408;
    uint32_t* Ps   = sm + 26112;
    float*    redM = (float*)(sm + 30720);
    float*    redS = (float*)(sm + 30848);
    int*      maskS= (int*)(sm + 30976);

    const int tid  = threadIdx.x;
    const int wid  = tid >> 5;
    const int lane = tid & 31;
    const int g    = lane >> 2;
    const int tig  = lane & 3;
    const int wm   = wid & 3;
    const int wn   = wid >> 2;

    const int qb  = blockIdx.x;
    const int h   = blockIdx.y;
    const int b   = blockIdx.z;
    const int kvh = h >> 2;
    const int causal = causal_p[0];

    const float scale = 0.08838834764831845f;  // 1/sqrt(128)

    {
        const float* qbase = g_q + ((size_t)b * TT + qb * 64) * 2048 + h * HDIM;
        #pragma unroll
        for (int it = 0; it < 8; it++) {
            int task = tid + 256 * it;
            int r = task >> 5;
            int c = (task & 31) << 2;
            float4 f = *(const float4*)(qbase + (size_t)r * 2048 + c);
            uint32_t* dst = &Qs[r * KP + c];
            dst[0] = f32_to_tf32(f.x * scale);
            dst[1] = f32_to_tf32(f.y * scale);
            dst[2] = f32_to_tf32(f.z * scale);
            dst[3] = f32_to_tf32(f.w * scale);
        }
    }

    const int r0 = 16 * wm + g;
    const int r1 = r0 + 8;
    const int qg0 = qb * 64 + r0;
    const int qg1 = qb * 64 + r1;

    float accO[8][4];
    #pragma unroll
    for (int nt = 0; nt < 8; nt++)
        #pragma unroll
        for (int c = 0; c < 4; c++) accO[nt][c] = 0.0f;

    float m0 = -1e30f, m1 = -1e30f, l0 = 0.0f, l1 = 0.0f;

    const float* kbase = g_k + (size_t)b * TT * 512 + kvh * HDIM;
    const float* vbase = g_v + (size_t)b * TT * 512 + kvh * HDIM;
    const int kbmax = causal ? qb : (TT / 64 - 1);

    for (int kb = 0; kb <= kbmax; kb++) {
        const int kr0 = kb * 64;

        __syncthreads();

        #pragma unroll
        for (int it = 0; it < 8; it++) {
            int task = tid + 256 * it;
            int r = task >> 5;
            int c = (task & 31) << 2;
            float4 f = *(const float4*)(kbase + (size_t)(kr0 + r) * 512 + c);
            uint32_t* dst = &Ks[r * KP + c];
            dst[0] = f32_to_tf32(f.x);
            dst[1] = f32_to_tf32(f.y);
            dst[2] = f32_to_tf32(f.z);
            dst[3] = f32_to_tf32(f.w);
            float4 v = *(const float4*)(vbase + (size_t)(kr0 + r) * 512 + c);
            uint32_t* dvv = &Vs[r * KP + c];
            dvv[0] = f32_to_tf32(v.x);
            dvv[1] = f32_to_tf32(v.y);
            dvv[2] = f32_to_tf32(v.z);
            dvv[3] = f32_to_tf32(v.w);
        }
        if (tid < 64) maskS[tid] = mask[b * TT + kr0 + tid];
        __syncthreads();

        float sacc[4][4];
        #pragma unroll
        for (int nt = 0; nt < 4; nt++)
            #pragma unroll
            for (int c = 0; c < 4; c++) sacc[nt][c] = 0.0f;

        #pragma unroll
        for (int ks = 0; ks < 16; ks++) {
            const uint32_t* qr = &Qs[r0 * KP + ks * 8 + tig];
            uint32_t a0 = qr[0];
            uint32_t a2 = qr[4];
            uint32_t a1 = qr[8 * KP];
            uint32_t a3 = qr[8 * KP + 4];
            #pragma unroll
            for (int nt = 0; nt < 4; nt++) {
                const uint32_t* kr = &Ks[(32 * wn + 8 * nt + g) * KP + ks * 8 + tig];
                mma_tf32(sacc[nt], a0, a1, a2, a3, kr[0], kr[4]);
            }
        }

        float lm0 = -1e30f, lm1 = -1e30f;
        #pragma unroll
        for (int nt = 0; nt < 4; nt++) {
            #pragma unroll
            for (int e = 0; e < 2; e++) {
                int c  = 32 * wn + 8 * nt + 2 * tig + e;
                int kg = kr0 + c;
                bool mz = (maskS[c] == 0);
                if (mz || (causal && kg > qg0)) sacc[nt][e]     = -1e30f;
                if (mz || (causal && kg > qg1)) sacc[nt][e + 2] = -1e30f;
                lm0 = fmaxf(lm0, sacc[nt][e]);
                lm1 = fmaxf(lm1, sacc[nt][e + 2]);
            }
        }
        lm0 = fmaxf(lm0, __shfl_xor_sync(0xffffffffu, lm0, 1));
        lm0 = fmaxf(lm0, __shfl_xor_sync(0xffffffffu, lm0, 2));
        lm1 = fmaxf(lm1, __shfl_xor_sync(0xffffffffu, lm1, 1));
        lm1 = fmaxf(lm1, __shfl_xor_sync(0xffffffffu, lm1, 2));
        if (tig == 0) {
            redM[wn * 64 + r0] = lm0;
            redM[wn * 64 + r1] = lm1;
        }
        __syncthreads();

        float mn0 = fmaxf(m0, fmaxf(redM[r0], redM[64 + r0]));
        float mn1 = fmaxf(m1, fmaxf(redM[r1], redM[64 + r1]));
        float esc0 = __expf(m0 - mn0);
        float esc1 = __expf(m1 - mn1);

        float ls0 = 0.0f, ls1 = 0.0f;
        #pragma unroll
        for (int nt = 0; nt < 4; nt++) {
            float p0 = __expf(sacc[nt][0] - mn0);
            float p1 = __expf(sacc[nt][1] - mn0);
            float p2 = __expf(sacc[nt][2] - mn1);
            float p3 = __expf(sacc[nt][3] - mn1);
            ls0 += p0 + p1;
            ls1 += p2 + p3;
            int c = 32 * wn + 8 * nt + 2 * tig;
            uint32_t* d0 = &Ps[r0 * PP + c];
            uint32_t* d1 = &Ps[r1 * PP + c];
            d0[0] = f32_to_tf32(p0);
            d0[1] = f32_to_tf32(p1);
            d1[0] = f32_to_tf32(p2);
            d1[1] = f32_to_tf32(p3);
        }
        ls0 += __shfl_xor_sync(0xffffffffu, ls0, 1);
        ls0 += __shfl_xor_sync(0xffffffffu, ls0, 2);
        ls1 += __shfl_xor_sync(0xffffffffu, ls1, 1);
        ls1 += __shfl_xor_sync(0xffffffffu, ls1, 2);
        if (tig == 0) {
            redS[wn * 64 + r0] = ls0;
            redS[wn * 64 + r1] = ls1;
        }

        #pragma unroll
        for (int nt = 0; nt < 8; nt++) {
            accO[nt][0] *= esc0; accO[nt][1] *= esc0;
            accO[nt][2] *= esc1; accO[nt][3] *= esc1;
        }
        __syncthreads();

        l0 = l0 * esc0 + redS[r0] + redS[64 + r0];
        l1 = l1 * esc1 + redS[r1] + redS[64 + r1];
        m0 = mn0;
        m1 = mn1;

        #pragma unroll
        for (int ks = 0; ks < 8; ks++) {
            const uint32_t* pr = &Ps[r0 * PP + ks * 8 + tig];
            uint32_t a0 = pr[0];
            uint32_t a2 = pr[4];
            uint32_t a1 = pr[8 * PP];
            uint32_t a3 = pr[8 * PP + 4];
            #pragma unroll
            for (int nt = 0; nt < 8; nt++) {
                const uint32_t* vr = &Vs[(ks * 8 + tig) * KP + 64 * wn + 8 * nt + g];
                mma_tf32(accO[nt], a0, a1, a2, a3, vr[0], vr[4 * KP]);
            }
        }
    }

    float invl0 = 1.0f / l0;
    float invl1 = 1.0f / l1;
    float* ob0 = g_o + ((size_t)b * TT + qb * 64 + r0) * 2048 + h * HDIM + 64 * wn + 2 * tig;
    float* ob1 = g_o + ((size_t)b * TT + qb * 64 + r1) * 2048 + h * HDIM + 64 * wn + 2 * tig;
    #pragma unroll
    for (int nt = 0; nt < 8; nt++) {
        *(float2*)(ob0 + 8 * nt) = make_float2(accO[nt][0] * invl0, accO[nt][1] * invl0);
        *(float2*)(ob1 + 8 * nt) = make_float2(accO[nt][2] * invl1, accO[nt][3] * invl1);
    }
}

// ---------------------------------------------------------------------------
extern "C" void kernel_launch(void* const* d_in, const int* in_sizes, int n_in,
                              void* d_out, int out_size) {
    const float* x      = (const float*)d_in[0];
    const int*   mask   = (const int*)d_in[1];
    const int*   causal = (const int*)d_in[2];
    const float* wq     = (const float*)d_in[3];
    const float* wk     = (const float*)d_in[4];
    const float* wv     = (const float*)d_in[5];
    const float* wo     = (const float*)d_in[6];
    float* out = (float*)d_out;

    float *gq, *gk, *gv, *go;
    cudaGetSymbolAddress((void**)&gq, g_q);
    cudaGetSymbolAddress((void**)&gk, g_k);
    cudaGetSymbolAddress((void**)&gv, g_v);
    cudaGetSymbolAddress((void**)&go, g_o);

    const int M = BB * TT;  // 4096

    cudaFuncSetAttribute(qkv_gemm_kernel, cudaFuncAttributeMaxDynamicSharedMemorySize,
                         GEMM_SMEM_BYTES);
    cudaFuncSetAttribute(tf32_gemm_kernel, cudaFuncAttributeMaxDynamicSharedMemorySize,
                         GEMM_SMEM_BYTES);
    cudaFuncSetAttribute(attn_mma_kernel, cudaFuncAttributeMaxDynamicSharedMemorySize,
                         ATTN_SMEM_BYTES);

    // Fused QKV projection
    qkv_gemm_kernel<<<dim3(24, M / 128), 256, GEMM_SMEM_BYTES>>>(
        x, wq, wk, wv, gq, gk, gv);

    // RoPE
    int rope_threads = BB * TT * (NH + NKV) * 64;
    rope_kernel<<<(rope_threads + 255) / 256, 256>>>();

    // Attention (tensor cores)
    attn_mma_kernel<<<dim3(TT / 64, NH, BB), 256, ATTN_SMEM_BYTES>>>(mask, causal);

    // Output projection
    tf32_gemm_kernel<<<dim3(DD / 128, M / 128), 256, GEMM_SMEM_BYTES>>>(
        go, wo, out, M, DD, DD);
}

// round 5
// speedup vs baseline: 3.8102x; 1.0559x over previous
#include <cuda_runtime.h>
#include <math.h>
#include <stdint.h>

#define BB   2
#define TT   2048
#define DD   2048
#define NH   16
#define NKV  4
#define HDIM 128

// Scratch (allocation-free rule: __device__ globals)
__device__ float g_q[BB*TT*NH*HDIM];    // [B*T, 2048]
__device__ float g_k[BB*TT*NKV*HDIM];   // [B*T, 512]
__device__ float g_v[BB*TT*NKV*HDIM];   // [B*T, 512]
__device__ float g_o[BB*TT*NH*HDIM];    // [B*T, 2048] (tf32-rounded by attn)
// tf32-preconverted operands
__device__ float g_xt [BB*TT*DD];       // x   as tf32 bits
__device__ float g_wqt[DD*NH*HDIM];
__device__ float g_wkt[DD*NKV*HDIM];
__device__ float g_wvt[DD*NKV*HDIM];
__device__ float g_wot[DD*DD];

__device__ __forceinline__ uint32_t f32_to_tf32(float x) {
    uint32_t r;
    asm("cvt.rna.tf32.f32 %0, %1;" : "=r"(r) : "f"(x));
    return r;
}

__device__ __forceinline__ void mma_tf32(float c[4],
                                         uint32_t a0, uint32_t a1, uint32_t a2, uint32_t a3,
                                         uint32_t b0, uint32_t b1) {
    asm volatile(
        "mma.sync.aligned.m16n8k8.row.col.f32.tf32.tf32.f32 "
        "{%0,%1,%2,%3}, {%4,%5,%6,%7}, {%8,%9}, {%0,%1,%2,%3};\n"
        : "+f"(c[0]), "+f"(c[1]), "+f"(c[2]), "+f"(c[3])
        : "r"(a0), "r"(a1), "r"(a2), "r"(a3), "r"(b0), "r"(b1));
}

__device__ __forceinline__ void cp_async16(uint32_t smem_addr, const void* gptr) {
    asm volatile("cp.async.cg.shared.global [%0], [%1], 16;\n"
                 :: "r"(smem_addr), "l"(gptr));
}
__device__ __forceinline__ void cp_commit() {
    asm volatile("cp.async.commit_group;\n" ::: "memory");
}
template <int N>
__device__ __forceinline__ void cp_wait() {
    asm volatile("cp.async.wait_group %0;\n" :: "n"(N) : "memory");
}

// ---------------------------------------------------------------------------
// tf32 pre-conversion (elementwise, float4)
// ---------------------------------------------------------------------------
__global__ __launch_bounds__(256)
void cvt_tf32_kernel(const float4* __restrict__ src, float4* __restrict__ dst, int n4) {
    int i = blockIdx.x * blockDim.x + threadIdx.x;
    if (i < n4) {
        float4 f = src[i];
        float4 o;
        o.x = __uint_as_float(f32_to_tf32(f.x));
        o.y = __uint_as_float(f32_to_tf32(f.y));
        o.z = __uint_as_float(f32_to_tf32(f.z));
        o.w = __uint_as_float(f32_to_tf32(f.w));
        dst[i] = o;
    }
}

// ---------------------------------------------------------------------------
// TF32 tensor-core GEMM body, cp.async double-buffered, operands pre-tf32.
// BM=128, BN=128, BK=32, 256 threads, warp tile 64x32.
// ---------------------------------------------------------------------------
#define APITCH 36
#define BPITCH 136
#define ASZ    (128 * APITCH)
#define BSZ    (32 * BPITCH)
#define STG    (ASZ + BSZ)
#define GEMM_SMEM_BYTES (2 * STG * 4)

__device__ __forceinline__ void gemm_body(
    const float* __restrict__ A,   // [.,K] tf32 bits, row block applied
    const float* __restrict__ B,   // [K,N] tf32 bits, col block applied
    float* __restrict__ C,
    int N, int K, uint32_t smem_base)
{
    const int tid  = threadIdx.x;
    const int wid  = tid >> 5;
    const int lane = tid & 31;
    const int g    = lane >> 2;
    const int tig  = lane & 3;

    const int warp_m = (wid & 1) * 64;
    const int warp_n = (wid >> 1) * 32;

    uint32_t* sm = (uint32_t*)__cvta_shared_to_generic(smem_base);

    const int a_row = tid >> 1;
    const int a_c4  = (tid & 1) << 4;
    const int b_kr  = tid >> 5;
    const int b_c4  = lane << 2;

    const uint32_t aAddr = smem_base;
    const uint32_t bAddr = smem_base + ASZ * 4;

    float acc[4][4][4];
    #pragma unroll
    for (int i = 0; i < 4; i++)
        #pragma unroll
        for (int j = 0; j < 4; j++)
            #pragma unroll
            for (int c = 0; c < 4; c++) acc[i][j][c] = 0.0f;

    const int niter = K >> 5;

    {
        const float* srcA = A + (size_t)a_row * K + a_c4;
        uint32_t dstA = aAddr + (a_row * APITCH + a_c4) * 4;
        #pragma unroll
        for (int v = 0; v < 4; v++)
            cp_async16(dstA + v * 16, srcA + v * 4);
        #pragma unroll
        for (int v = 0; v < 4; v++) {
            int kr = b_kr + v * 8;
            cp_async16(bAddr + (kr * BPITCH + b_c4) * 4,
                       B + (size_t)kr * N + b_c4);
        }
        cp_commit();
    }

    for (int i = 0; i < niter; i++) {
        const int cur = i & 1;
        if (i + 1 < niter) {
            const int nxt = cur ^ 1;
            const int k0 = (i + 1) << 5;
            const float* srcA = A + (size_t)a_row * K + k0 + a_c4;
            uint32_t dstA = aAddr + (nxt * STG + a_row * APITCH + a_c4) * 4;
            #pragma unroll
            for (int v = 0; v < 4; v++)
                cp_async16(dstA + v * 16, srcA + v * 4);
            #pragma unroll
            for (int v = 0; v < 4; v++) {
                int kr = b_kr + v * 8;
                cp_async16(bAddr + (nxt * STG + kr * BPITCH + b_c4) * 4,
                           B + (size_t)(k0 + kr) * N + b_c4);
            }
            cp_commit();
            cp_wait<1>();
        } else {
            cp_wait<0>();
        }
        __syncthreads();

        const uint32_t* As = sm + cur * STG;
        const uint32_t* Bs = As + ASZ;

        #pragma unroll
        for (int ks = 0; ks < 4; ks++) {
            const int kk = ks * 8;
            uint32_t af[4][4];
            #pragma unroll
            for (int mt = 0; mt < 4; mt++) {
                int ar = warp_m + mt * 16 + g;
                af[mt][0] = As[ar * APITCH + kk + tig];
                af[mt][1] = As[(ar + 8) * APITCH + kk + tig];
                af[mt][2] = As[ar * APITCH + kk + tig + 4];
                af[mt][3] = As[(ar + 8) * APITCH + kk + tig + 4];
            }
            uint32_t bf[4][2];
            #pragma unroll
            for (int nt = 0; nt < 4; nt++) {
                int bc = warp_n + nt * 8 + g;
                bf[nt][0] = Bs[(kk + tig) * BPITCH + bc];
                bf[nt][1] = Bs[(kk + tig + 4) * BPITCH + bc];
            }
            #pragma unroll
            for (int mt = 0; mt < 4; mt++)
                #pragma unroll
                for (int nt = 0; nt < 4; nt++)
                    mma_tf32(acc[mt][nt], af[mt][0], af[mt][1], af[mt][2], af[mt][3],
                             bf[nt][0], bf[nt][1]);
        }
        __syncthreads();
    }

    float* Cw = C + (size_t)warp_m * N + warp_n;
    #pragma unroll
    for (int mt = 0; mt < 4; mt++) {
        #pragma unroll
        for (int nt = 0; nt < 4; nt++) {
            int row = mt * 16 + g;
            int col = nt * 8 + 2 * tig;
            *(float2*)(Cw + (size_t)row * N + col) =
                make_float2(acc[mt][nt][0], acc[mt][nt][1]);
            *(float2*)(Cw + (size_t)(row + 8) * N + col) =
                make_float2(acc[mt][nt][2], acc[mt][nt][3]);
        }
    }
}

// Fused QKV projection: grid.x = 24 column tiles (16 q, 4 k, 4 v), grid.y = 32.
__global__ __launch_bounds__(256, 2)
void qkv_gemm_kernel(float* __restrict__ gq, float* __restrict__ gk,
                     float* __restrict__ gv) {
    extern __shared__ uint32_t smraw[];
    uint32_t smem_base = (uint32_t)__cvta_generic_to_shared(smraw);

    const int bx = blockIdx.x;
    const int by = blockIdx.y;

    const float* Bsel;
    float* Csel;
    int Nsel, colb;
    if (bx < 16)      { Bsel = g_wqt; Csel = gq; Nsel = 2048; colb = bx * 128; }
    else if (bx < 20) { Bsel = g_wkt; Csel = gk; Nsel = 512;  colb = (bx - 16) * 128; }
    else              { Bsel = g_wvt; Csel = gv; Nsel = 512;  colb = (bx - 20) * 128; }

    gemm_body(g_xt + (size_t)by * 128 * DD,
              Bsel + colb,
              Csel + (size_t)by * 128 * Nsel + colb,
              Nsel, DD, smem_base);
}

// Output projection: grid (N/128, M/128)
__global__ __launch_bounds__(256, 2)
void wo_gemm_kernel(float* __restrict__ C) {
    extern __shared__ uint32_t smraw[];
    uint32_t smem_base = (uint32_t)__cvta_generic_to_shared(smraw);
    const int bx = blockIdx.x;
    const int by = blockIdx.y;
    gemm_body(g_o + (size_t)by * 128 * DD,
              g_wot + bx * 128,
              C + (size_t)by * 128 * DD + bx * 128,
              DD, DD, smem_base);
}

// ---------------------------------------------------------------------------
// RoPE in-place on g_q and g_k
// ---------------------------------------------------------------------------
#define LOG2_THETA_OVER_HALF 0.20762050593046128f   // log2(10000)/64

__global__ __launch_bounds__(256)
void rope_kernel() {
    const int totq = BB * TT * NH * 64;
    const int totk = BB * TT * NKV * 64;
    int idx = blockIdx.x * blockDim.x + threadIdx.x;
    if (idx < totq) {
        int d  = idx & 63;
        int h  = (idx >> 6) % NH;
        int bt = idx / (64 * NH);
        int t  = bt & (TT - 1);
        float inv = exp2f(-(float)d * LOG2_THETA_OVER_HALF);
        float ang = (float)t * inv;
        float s, c;
        sincosf(ang, &s, &c);
        float* p = g_q + (size_t)bt * (NH * HDIM) + h * HDIM;
        float x1 = p[d], x2 = p[d + 64];
        p[d]      = x1 * c - x2 * s;
        p[d + 64] = x2 * c + x1 * s;
    } else if (idx < totq + totk) {
        int j  = idx - totq;
        int d  = j & 63;
        int h  = (j >> 6) % NKV;
        int bt = j / (64 * NKV);
        int t  = bt & (TT - 1);
        float inv = exp2f(-(float)d * LOG2_THETA_OVER_HALF);
        float ang = (float)t * inv;
        float s, c;
        sincosf(ang, &s, &c);
        float* p = g_k + (size_t)bt * (NKV * HDIM) + h * HDIM;
        float x1 = p[d], x2 = p[d + 64];
        p[d]      = x1 * c - x2 * s;
        p[d + 64] = x2 * c + x1 * s;
    }
}

// ---------------------------------------------------------------------------
// Tensor-core flash attention (tf32 mma), BM=128, BN=64, HD=128.
// 8 warps, each warp owns 16 query rows across the full key tile:
// row-stats are warp-local (no cross-warp reduction).
// smem (uint32 words):
//   Qs [128][136] : 0       (17408)
//   Ks [64][136]  : 17408   (8704)
//   Vs [64][136]  : 26112   (8704)
//   Ps [128][72]  : 34816   (9216)
//   maskS int[64] : 44032
// total 44096 words = 176384 bytes
// ---------------------------------------------------------------------------
#define KP 136
#define PP 72
#define ATTN_SMEM_BYTES (44096 * 4)

__global__ __launch_bounds__(256, 1)
void attn_mma_kernel(const int* __restrict__ mask, const int* __restrict__ causal_p) {
    extern __shared__ uint32_t sm[];
    uint32_t* Qs    = sm;
    uint32_t* Ks    = sm + 17408;
    uint32_t* Vs    = sm + 26112;
    uint32_t* Ps    = sm + 34816;
    int*      maskS = (int*)(sm + 44032);

    const int tid  = threadIdx.x;
    const int wid  = tid >> 5;
    const int lane = tid & 31;
    const int g    = lane >> 2;
    const int tig  = lane & 3;

    const int qb  = blockIdx.x;   // 128-row query block
    const int h   = blockIdx.y;
    const int b   = blockIdx.z;
    const int kvh = h >> 2;
    const int causal = causal_p[0];

    const float scale = 0.08838834764831845f;  // 1/sqrt(128)

    // ---- load Q tile (128 x 128) as tf32, pre-scaled ----
    {
        const float* qbase = g_q + ((size_t)b * TT + qb * 128) * 2048 + h * HDIM;
        #pragma unroll
        for (int it = 0; it < 16; it++) {
            int task = tid + 256 * it;
            int r = task >> 5;
            int c = (task & 31) << 2;
            float4 f = *(const float4*)(qbase + (size_t)r * 2048 + c);
            uint32_t* dst = &Qs[r * KP + c];
            dst[0] = f32_to_tf32(f.x * scale);
            dst[1] = f32_to_tf32(f.y * scale);
            dst[2] = f32_to_tf32(f.z * scale);
            dst[3] = f32_to_tf32(f.w * scale);
        }
    }

    const int r0  = 16 * wid + g;
    const int r1  = r0 + 8;
    const int qg0 = qb * 128 + r0;
    const int qg1 = qb * 128 + r1;

    float accO[16][4];
    #pragma unroll
    for (int nt = 0; nt < 16; nt++)
        #pragma unroll
        for (int c = 0; c < 4; c++) accO[nt][c] = 0.0f;

    float m0 = -1e30f, m1 = -1e30f, l0 = 0.0f, l1 = 0.0f;

    const float* kbase = g_k + (size_t)b * TT * 512 + kvh * HDIM;
    const float* vbase = g_v + (size_t)b * TT * 512 + kvh * HDIM;
    const int kbmax = causal ? (2 * qb + 1) : (TT / 64 - 1);

    for (int kb = 0; kb <= kbmax; kb++) {
        const int kr0 = kb * 64;

        __syncthreads();   // prior P@V done reading Vs

        // ---- fill K and V tiles (64 x 128 each) as tf32 ----
        #pragma unroll
        for (int it = 0; it < 8; it++) {
            int task = tid + 256 * it;
            int r = task >> 5;
            int c = (task & 31) << 2;
            float4 f = *(const float4*)(kbase + (size_t)(kr0 + r) * 512 + c);
            uint32_t* dst = &Ks[r * KP + c];
            dst[0] = f32_to_tf32(f.x);
            dst[1] = f32_to_tf32(f.y);
            dst[2] = f32_to_tf32(f.z);
            dst[3] = f32_to_tf32(f.w);
            float4 v = *(const float4*)(vbase + (size_t)(kr0 + r) * 512 + c);
            uint32_t* dvv = &Vs[r * KP + c];
            dvv[0] = f32_to_tf32(v.x);
            dvv[1] = f32_to_tf32(v.y);
            dvv[2] = f32_to_tf32(v.z);
            dvv[3] = f32_to_tf32(v.w);
        }
        if (tid < 64) maskS[tid] = mask[b * TT + kr0 + tid];
        __syncthreads();

        // ---- S = Q @ K^T : warp computes 16 x 64 ----
        float sacc[8][4];
        #pragma unroll
        for (int nt = 0; nt < 8; nt++)
            #pragma unroll
            for (int c = 0; c < 4; c++) sacc[nt][c] = 0.0f;

        #pragma unroll
        for (int ks = 0; ks < 16; ks++) {
            const uint32_t* qr = &Qs[r0 * KP + ks * 8 + tig];
            uint32_t a0 = qr[0];
            uint32_t a2 = qr[4];
            uint32_t a1 = qr[8 * KP];
            uint32_t a3 = qr[8 * KP + 4];
            #pragma unroll
            for (int nt = 0; nt < 8; nt++) {
                const uint32_t* kr = &Ks[(8 * nt + g) * KP + ks * 8 + tig];
                mma_tf32(sacc[nt], a0, a1, a2, a3, kr[0], kr[4]);
            }
        }

        // ---- mask + warp-local row max ----
        float lm0 = -1e30f, lm1 = -1e30f;
        #pragma unroll
        for (int nt = 0; nt < 8; nt++) {
            #pragma unroll
            for (int e = 0; e < 2; e++) {
                int c  = 8 * nt + 2 * tig + e;
                int kg = kr0 + c;
                bool mz = (maskS[c] == 0);
                if (mz || (causal && kg > qg0)) sacc[nt][e]     = -1e30f;
                if (mz || (causal && kg > qg1)) sacc[nt][e + 2] = -1e30f;
                lm0 = fmaxf(lm0, sacc[nt][e]);
                lm1 = fmaxf(lm1, sacc[nt][e + 2]);
            }
        }
        lm0 = fmaxf(lm0, __shfl_xor_sync(0xffffffffu, lm0, 1));
        lm0 = fmaxf(lm0, __shfl_xor_sync(0xffffffffu, lm0, 2));
        lm1 = fmaxf(lm1, __shfl_xor_sync(0xffffffffu, lm1, 1));
        lm1 = fmaxf(lm1, __shfl_xor_sync(0xffffffffu, lm1, 2));

        float mn0 = fmaxf(m0, lm0);
        float mn1 = fmaxf(m1, lm1);
        float esc0 = __expf(m0 - mn0);
        float esc1 = __expf(m1 - mn1);

        // ---- p = exp(s - m), row sums (warp-local), write P ----
        float ls0 = 0.0f, ls1 = 0.0f;
        #pragma unroll
        for (int nt = 0; nt < 8; nt++) {
            float p0 = __expf(sacc[nt][0] - mn0);
            float p1 = __expf(sacc[nt][1] - mn0);
            float p2 = __expf(sacc[nt][2] - mn1);
            float p3 = __expf(sacc[nt][3] - mn1);
            ls0 += p0 + p1;
            ls1 += p2 + p3;
            int c = 8 * nt + 2 * tig;
            uint32_t* d0 = &Ps[r0 * PP + c];
            uint32_t* d1 = &Ps[r1 * PP + c];
            d0[0] = f32_to_tf32(p0);
            d0[1] = f32_to_tf32(p1);
            d1[0] = f32_to_tf32(p2);
            d1[1] = f32_to_tf32(p3);
        }
        ls0 += __shfl_xor_sync(0xffffffffu, ls0, 1);
        ls0 += __shfl_xor_sync(0xffffffffu, ls0, 2);
        ls1 += __shfl_xor_sync(0xffffffffu, ls1, 1);
        ls1 += __shfl_xor_sync(0xffffffffu, ls1, 2);

        l0 = l0 * esc0 + ls0;
        l1 = l1 * esc1 + ls1;
        m0 = mn0;
        m1 = mn1;

        // rescale accumulators
        #pragma unroll
        for (int nt = 0; nt < 16; nt++) {
            accO[nt][0] *= esc0; accO[nt][1] *= esc0;
            accO[nt][2] *= esc1; accO[nt][3] *= esc1;
        }
        __syncwarp();   // P visible to own warp

        // ---- O += P @ V : warp computes 16 x 128 ----
        #pragma unroll
        for (int ks = 0; ks < 8; ks++) {
            const uint32_t* pr = &Ps[r0 * PP + ks * 8 + tig];
            uint32_t a0 = pr[0];
            uint32_t a2 = pr[4];
            uint32_t a1 = pr[8 * PP];
            uint32_t a3 = pr[8 * PP + 4];
            #pragma unroll
            for (int nt = 0; nt < 16; nt++) {
                const uint32_t* vr = &Vs[(ks * 8 + tig) * KP + 8 * nt + g];
                mma_tf32(accO[nt], a0, a1, a2, a3, vr[0], vr[4 * KP]);
            }
        }
    }

    // ---- epilogue: normalize, round to tf32, write ----
    float invl0 = 1.0f / l0;
    float invl1 = 1.0f / l1;
    float* ob0 = g_o + ((size_t)b * TT + qb * 128 + r0) * 2048 + h * HDIM + 2 * tig;
    float* ob1 = g_o + ((size_t)b * TT + qb * 128 + r1) * 2048 + h * HDIM + 2 * tig;
    #pragma unroll
    for (int nt = 0; nt < 16; nt++) {
        *(float2*)(ob0 + 8 * nt) = make_float2(
            __uint_as_float(f32_to_tf32(accO[nt][0] * invl0)),
            __uint_as_float(f32_to_tf32(accO[nt][1] * invl0)));
        *(float2*)(ob1 + 8 * nt) = make_float2(
            __uint_as_float(f32_to_tf32(accO[nt][2] * invl1)),
            __uint_as_float(f32_to_tf32(accO[nt][3] * invl1)));
    }
}

// ---------------------------------------------------------------------------
extern "C" void kernel_launch(void* const* d_in, const int* in_sizes, int n_in,
                              void* d_out, int out_size) {
    const float* x      = (const float*)d_in[0];
    const int*   mask   = (const int*)d_in[1];
    const int*   causal = (const int*)d_in[2];
    const float* wq     = (const float*)d_in[3];
    const float* wk     = (const float*)d_in[4];
    const float* wv     = (const float*)d_in[5];
    const float* wo     = (const float*)d_in[6];
    float* out = (float*)d_out;

    float *gq, *gk, *gv, *xt, *wqt, *wkt, *wvt, *wot;
    cudaGetSymbolAddress((void**)&gq,  g_q);
    cudaGetSymbolAddress((void**)&gk,  g_k);
    cudaGetSymbolAddress((void**)&gv,  g_v);
    cudaGetSymbolAddress((void**)&xt,  g_xt);
    cudaGetSymbolAddress((void**)&wqt, g_wqt);
    cudaGetSymbolAddress((void**)&wkt, g_wkt);
    cudaGetSymbolAddress((void**)&wvt, g_wvt);
    cudaGetSymbolAddress((void**)&wot, g_wot);

    const int M = BB * TT;  // 4096

    cudaFuncSetAttribute(qkv_gemm_kernel, cudaFuncAttributeMaxDynamicSharedMemorySize,
                         GEMM_SMEM_BYTES);
    cudaFuncSetAttribute(wo_gemm_kernel, cudaFuncAttributeMaxDynamicSharedMemorySize,
                         GEMM_SMEM_BYTES);
    cudaFuncSetAttribute(attn_mma_kernel, cudaFuncAttributeMaxDynamicSharedMemorySize,
                         ATTN_SMEM_BYTES);

    // Pre-convert operands to tf32
    {
        int n4;
        n4 = (M * DD) / 4;
        cvt_tf32_kernel<<<(n4 + 255) / 256, 256>>>((const float4*)x,  (float4*)xt,  n4);
        n4 = (DD * NH * HDIM) / 4;
        cvt_tf32_kernel<<<(n4 + 255) / 256, 256>>>((const float4*)wq, (float4*)wqt, n4);
        n4 = (DD * NKV * HDIM) / 4;
        cvt_tf32_kernel<<<(n4 + 255) / 256, 256>>>((const float4*)wk, (float4*)wkt, n4);
        cvt_tf32_kernel<<<(n4 + 255) / 256, 256>>>((const float4*)wv, (float4*)wvt, n4);
        n4 = (DD * DD) / 4;
        cvt_tf32_kernel<<<(n4 + 255) / 256, 256>>>((const float4*)wo, (float4*)wot, n4);
    }

    // Fused QKV projection
    qkv_gemm_kernel<<<dim3(24, M / 128), 256, GEMM_SMEM_BYTES>>>(gq, gk, gv);

    // RoPE
    int rope_threads = BB * TT * (NH + NKV) * 64;
    rope_kernel<<<(rope_threads + 255) / 256, 256>>>();

    // Attention (tensor cores), BM=128
    attn_mma_kernel<<<dim3(TT / 128, NH, BB), 256, ATTN_SMEM_BYTES>>>(mask, causal);

    // Output projection
    wo_gemm_kernel<<<dim3(DD / 128, M / 128), 256, GEMM_SMEM_BYTES>>>(out);
}